// round 1
// baseline (speedup 1.0000x reference)
#include <cuda_runtime.h>
#include <math.h>

// Problem constants
#define NDIM 8192
#define HDIM 512
#define TAU_INV 2.0f     // 1/0.5
#define EPSV 1e-8f

// Tiling
constexpr int BM = 128, BN = 128, BK = 16;
constexpr int NTHREADS = 256;   // 16x16 thread grid, 8x8 per thread

// Scratch (static device memory; no allocation allowed)
__device__ float g_h[2ull * NDIM * HDIM];   // hidden activations for both inputs (32 MB)
__device__ float g_inv0[NDIM];
__device__ float g_inv1[NDIM];
__device__ float g_S[NDIM];
__device__ float g_P[NDIM];

// ---------------------------------------------------------------------------
// GEMM: C = act(A @ B^T + bias). A:[M,K] row-major, B:[Nn,K] row-major.
// blockIdx.z selects (A0,C0) vs (A1,C1) so both MLP branches run in one launch.
// doElu: 1 -> ELU(alpha=1), 0 -> identity.
// M=NDIM, Nn=HDIM, K=HDIM; all divisible by tile sizes, no bounds checks.
// ---------------------------------------------------------------------------
__global__ __launch_bounds__(NTHREADS) void gemm_bias_act(
    const float* __restrict__ A0, const float* __restrict__ A1,
    const float* __restrict__ B, const float* __restrict__ bias,
    float* __restrict__ C0, float* __restrict__ C1,
    int K, int Nn, int doElu)
{
    __shared__ float As[BK][BM + 4];
    __shared__ float Bs[BK][BN + 4];

    const float* A = (blockIdx.z == 0) ? A0 : A1;
    float* C = (blockIdx.z == 0) ? C0 : C1;

    const int t = threadIdx.x;
    const int tx = t & 15;
    const int ty = t >> 4;
    const int rowBase = blockIdx.y * BM;
    const int colBase = blockIdx.x * BN;

    float acc[8][8];
#pragma unroll
    for (int i = 0; i < 8; i++)
#pragma unroll
        for (int j = 0; j < 8; j++) acc[i][j] = 0.0f;

    for (int k0 = 0; k0 < K; k0 += BK) {
        // Load 128x16 tiles of A and B (each thread: 2 float4 per matrix)
#pragma unroll
        for (int rep = 0; rep < 2; rep++) {
            int f = t + rep * 256;          // 0..511
            int row = f >> 2;               // 0..127
            int kq = (f & 3) << 2;          // 0,4,8,12
            float4 va = *reinterpret_cast<const float4*>(
                &A[(size_t)(rowBase + row) * K + k0 + kq]);
            As[kq + 0][row] = va.x; As[kq + 1][row] = va.y;
            As[kq + 2][row] = va.z; As[kq + 3][row] = va.w;
            float4 vb = *reinterpret_cast<const float4*>(
                &B[(size_t)(colBase + row) * K + k0 + kq]);
            Bs[kq + 0][row] = vb.x; Bs[kq + 1][row] = vb.y;
            Bs[kq + 2][row] = vb.z; Bs[kq + 3][row] = vb.w;
        }
        __syncthreads();

#pragma unroll
        for (int kk = 0; kk < BK; kk++) {
            float a[8], b[8];
            *reinterpret_cast<float4*>(&a[0]) =
                *reinterpret_cast<const float4*>(&As[kk][ty * 8]);
            *reinterpret_cast<float4*>(&a[4]) =
                *reinterpret_cast<const float4*>(&As[kk][ty * 8 + 4]);
            *reinterpret_cast<float4*>(&b[0]) =
                *reinterpret_cast<const float4*>(&Bs[kk][tx * 8]);
            *reinterpret_cast<float4*>(&b[4]) =
                *reinterpret_cast<const float4*>(&Bs[kk][tx * 8 + 4]);
#pragma unroll
            for (int i = 0; i < 8; i++)
#pragma unroll
                for (int j = 0; j < 8; j++) acc[i][j] += a[i] * b[j];
        }
        __syncthreads();
    }

    // Epilogue: bias + optional ELU, vectorized store
    float bv[8];
#pragma unroll
    for (int j = 0; j < 8; j++) bv[j] = bias[colBase + tx * 8 + j];

#pragma unroll
    for (int i = 0; i < 8; i++) {
        int row = rowBase + ty * 8 + i;
        float out[8];
#pragma unroll
        for (int j = 0; j < 8; j++) {
            float v = acc[i][j] + bv[j];
            if (doElu) v = (v > 0.0f) ? v : expm1f(v);
            out[j] = v;
        }
        *reinterpret_cast<float4*>(&C[(size_t)row * Nn + colBase + tx * 8]) =
            *reinterpret_cast<const float4*>(&out[0]);
        *reinterpret_cast<float4*>(&C[(size_t)row * Nn + colBase + tx * 8 + 4]) =
            *reinterpret_cast<const float4*>(&out[4]);
    }
}

// ---------------------------------------------------------------------------
// Row norms of z0/z1 (inverse norms) + zero the S/P accumulators.
// grid = 2*NDIM blocks of 128 threads (each thread loads exactly 1 float4).
// ---------------------------------------------------------------------------
__global__ void norm_init_kernel(const float* __restrict__ z0,
                                 const float* __restrict__ z1)
{
    int b = blockIdx.x;
    int row = (b < NDIM) ? b : (b - NDIM);
    const float* z = (b < NDIM) ? z0 : z1;

    float4 v = *reinterpret_cast<const float4*>(
        &z[(size_t)row * HDIM + threadIdx.x * 4]);
    float ss = v.x * v.x + v.y * v.y + v.z * v.z + v.w * v.w;
#pragma unroll
    for (int off = 16; off; off >>= 1)
        ss += __shfl_xor_sync(0xffffffffu, ss, off);

    __shared__ float sred[4];
    if ((threadIdx.x & 31) == 0) sred[threadIdx.x >> 5] = ss;
    __syncthreads();
    if (threadIdx.x == 0) {
        float tot = sred[0] + sred[1] + sred[2] + sred[3];
        float inv = 1.0f / sqrtf(tot);
        if (b < NDIM) {
            g_inv0[row] = inv;
            g_S[row] = 0.0f;
            g_P[row] = 0.0f;
        } else {
            g_inv1[row] = inv;
        }
    }
}

// ---------------------------------------------------------------------------
// Fused similarity: tile of dot = z0 @ z1^T, then m = exp(dot*inv0*inv1*TAU_INV),
// accumulate per-row S += m and P += m*pos without materializing the matrix.
// ---------------------------------------------------------------------------
__global__ __launch_bounds__(NTHREADS) void sim_fused_kernel(
    const float* __restrict__ z0, const float* __restrict__ z1,
    const float* __restrict__ pos)
{
    __shared__ float As[BK][BM + 4];
    __shared__ float Bs[BK][BN + 4];

    const int t = threadIdx.x;
    const int tx = t & 15;
    const int ty = t >> 4;
    const int rowBase = blockIdx.y * BM;
    const int colBase = blockIdx.x * BN;
    const int K = HDIM;

    float acc[8][8];
#pragma unroll
    for (int i = 0; i < 8; i++)
#pragma unroll
        for (int j = 0; j < 8; j++) acc[i][j] = 0.0f;

    for (int k0 = 0; k0 < K; k0 += BK) {
#pragma unroll
        for (int rep = 0; rep < 2; rep++) {
            int f = t + rep * 256;
            int row = f >> 2;
            int kq = (f & 3) << 2;
            float4 va = *reinterpret_cast<const float4*>(
                &z0[(size_t)(rowBase + row) * K + k0 + kq]);
            As[kq + 0][row] = va.x; As[kq + 1][row] = va.y;
            As[kq + 2][row] = va.z; As[kq + 3][row] = va.w;
            float4 vb = *reinterpret_cast<const float4*>(
                &z1[(size_t)(colBase + row) * K + k0 + kq]);
            Bs[kq + 0][row] = vb.x; Bs[kq + 1][row] = vb.y;
            Bs[kq + 2][row] = vb.z; Bs[kq + 3][row] = vb.w;
        }
        __syncthreads();

#pragma unroll
        for (int kk = 0; kk < BK; kk++) {
            float a[8], b[8];
            *reinterpret_cast<float4*>(&a[0]) =
                *reinterpret_cast<const float4*>(&As[kk][ty * 8]);
            *reinterpret_cast<float4*>(&a[4]) =
                *reinterpret_cast<const float4*>(&As[kk][ty * 8 + 4]);
            *reinterpret_cast<float4*>(&b[0]) =
                *reinterpret_cast<const float4*>(&Bs[kk][tx * 8]);
            *reinterpret_cast<float4*>(&b[4]) =
                *reinterpret_cast<const float4*>(&Bs[kk][tx * 8 + 4]);
#pragma unroll
            for (int i = 0; i < 8; i++)
#pragma unroll
                for (int j = 0; j < 8; j++) acc[i][j] += a[i] * b[j];
        }
        __syncthreads();
    }

    // Epilogue: exp(cos/tau), weighted by pos, per-row reduction
    float invj[8];
#pragma unroll
    for (int j = 0; j < 8; j++) invj[j] = g_inv1[colBase + tx * 8 + j];

#pragma unroll
    for (int i = 0; i < 8; i++) {
        int row = rowBase + ty * 8 + i;
        float invi = g_inv0[row];
        const float* prow = &pos[(size_t)row * NDIM + colBase + tx * 8];
        float4 p0 = *reinterpret_cast<const float4*>(&prow[0]);
        float4 p1 = *reinterpret_cast<const float4*>(&prow[4]);
        float pv[8] = {p0.x, p0.y, p0.z, p0.w, p1.x, p1.y, p1.z, p1.w};

        float s = 0.0f, p = 0.0f;
#pragma unroll
        for (int j = 0; j < 8; j++) {
            float m = expf(acc[i][j] * invi * invj[j] * TAU_INV);
            s += m;
            p += m * pv[j];
        }
        // reduce across the 16 tx-lanes (xor offsets stay within 16-lane half)
#pragma unroll
        for (int off = 8; off; off >>= 1) {
            s += __shfl_xor_sync(0xffffffffu, s, off);
            p += __shfl_xor_sync(0xffffffffu, p, off);
        }
        if (tx == 0) {
            atomicAdd(&g_S[row], s);
            atomicAdd(&g_P[row], p);
        }
    }
}

// ---------------------------------------------------------------------------
// Final loss: -mean(log(P/(S+eps)+eps))
// ---------------------------------------------------------------------------
__global__ void loss_kernel(float* __restrict__ loss_out)
{
    float local = 0.0f;
    for (int i = threadIdx.x; i < NDIM; i += 256) {
        local += logf(g_P[i] / (g_S[i] + EPSV) + EPSV);
    }
#pragma unroll
    for (int off = 16; off; off >>= 1)
        local += __shfl_xor_sync(0xffffffffu, local, off);

    __shared__ float sred[8];
    if ((threadIdx.x & 31) == 0) sred[threadIdx.x >> 5] = local;
    __syncthreads();
    if (threadIdx.x == 0) {
        float tot = 0.0f;
#pragma unroll
        for (int w = 0; w < 8; w++) tot += sred[w];
        loss_out[0] = -tot / (float)NDIM;
    }
}

// ---------------------------------------------------------------------------
// kernel_launch
// metadata order: embd0, embd1, pos, W1, b1, W2, b2
// output layout: [z0 (N*H) | z1 (N*H) | loss (1)]
// ---------------------------------------------------------------------------
extern "C" void kernel_launch(void* const* d_in, const int* in_sizes, int n_in,
                              void* d_out, int out_size)
{
    const float* embd0 = (const float*)d_in[0];
    const float* embd1 = (const float*)d_in[1];
    const float* pos   = (const float*)d_in[2];
    const float* W1    = (const float*)d_in[3];
    const float* b1    = (const float*)d_in[4];
    const float* W2    = (const float*)d_in[5];
    const float* b2    = (const float*)d_in[6];

    float* out = (float*)d_out;
    float* z0 = out;
    float* z1 = out + (size_t)NDIM * HDIM;
    float* loss = out + 2ull * NDIM * HDIM;

    float* h = nullptr;
    cudaGetSymbolAddress((void**)&h, g_h);
    float* h0 = h;
    float* h1 = h + (size_t)NDIM * HDIM;

    dim3 blk(NTHREADS);
    dim3 grid_mlp(HDIM / BN, NDIM / BM, 2);   // 4 x 64 x 2 = 512 blocks
    dim3 grid_sim(NDIM / BN, NDIM / BM);      // 64 x 64

    // MLP layer 1 (ELU) for both branches in one launch
    gemm_bias_act<<<grid_mlp, blk>>>(embd0, embd1, W1, b1, h0, h1,
                                     HDIM, HDIM, 1);
    // MLP layer 2 (linear) -> z0/z1 directly into d_out
    gemm_bias_act<<<grid_mlp, blk>>>(h0, h1, W2, b2, z0, z1,
                                     HDIM, HDIM, 0);
    // Inverse norms + zero accumulators
    norm_init_kernel<<<2 * NDIM, 128>>>(z0, z1);
    // Fused similarity + row reductions
    sim_fused_kernel<<<grid_sim, blk>>>(z0, z1, pos);
    // Scalar loss
    loss_kernel<<<1, 256>>>(loss);
}

// round 4
// speedup vs baseline: 1.9638x; 1.9638x over previous
#include <cuda_runtime.h>
#include <math.h>
#include <stdint.h>

// Problem constants
#define NDIM 8192
#define HDIM 512
#define TAU_INV 2.0f     // 1/0.5
#define EPSV 1e-8f

// Tiling (tensor-core version)
constexpr int BM = 128, BN = 128, BK = 32;
constexpr int NTHREADS = 256;   // 8 warps, arranged 2 (m) x 4 (n); warp tile 64x32

// Scratch (static device memory; no allocation allowed)
__device__ float g_h[2ull * NDIM * HDIM];   // hidden activations (32 MB)
__device__ float g_inv0[NDIM];
__device__ float g_inv1[NDIM];
__device__ float g_S[NDIM];
__device__ float g_P[NDIM];

__device__ __forceinline__ uint32_t f2tf32(float f) {
    uint32_t u;
    asm("cvt.rna.tf32.f32 %0, %1;" : "=r"(u) : "f"(f));
    return u;
}

__device__ __forceinline__ void mma_tf32(float c[4],
                                         const uint32_t a[4],
                                         const uint32_t b[2]) {
    asm volatile(
        "mma.sync.aligned.m16n8k8.row.col.f32.tf32.tf32.f32 "
        "{%0,%1,%2,%3}, {%4,%5,%6,%7}, {%8,%9}, {%0,%1,%2,%3};"
        : "+f"(c[0]), "+f"(c[1]), "+f"(c[2]), "+f"(c[3])
        : "r"(a[0]), "r"(a[1]), "r"(a[2]), "r"(a[3]),
          "r"(b[0]), "r"(b[1]));
}

// ---------------------------------------------------------------------------
// Fragment-ordered smem fill.
// A tile [BM x BK] (row-major source A[row][k]):
//   sA[(((mt*4)+ks)*32 + l)*4 + r], mt=row/16, ks=k/8,
//   l=(row%8)*4 + (k%4), r=((row/8)%2) + 2*((k%8)/4)
// B tile [BN x BK] (row-major source B[n][k]):
//   sB[(((nt*4)+ks)*32 + l)*2 + r], nt=n/8, ks=k/8,
//   l=(n%8)*4 + (k%4), r=(k%8)/4
// Each thread loads 4 float4 along k per tile (128 rows x 8 k-quads).
// ---------------------------------------------------------------------------
__device__ __forceinline__ void fill_tiles(
    uint32_t* sA, uint32_t* sB,
    const float* __restrict__ A, const float* __restrict__ B,
    int rowBase, int colBase, int K, int k0, int t)
{
#pragma unroll
    for (int v = 0; v < 4; v++) {
        int idx = t + v * 256;          // 0..1023
        int row = idx >> 3;             // 0..127
        int q   = idx & 7;              // k-quad (k = 4q..4q+3)
        int ks  = q >> 1;
        int e2  = q & 1;

        float4 va = *reinterpret_cast<const float4*>(
            &A[(size_t)(rowBase + row) * K + k0 + (q << 2)]);
        {
            int mt = row >> 4;
            int rr = row & 15;
            int r  = (rr >> 3) + (e2 << 1);
            uint32_t* p = &sA[(((((mt << 2) + ks) << 5) + ((rr & 7) << 2)) << 2) + r];
            p[0]  = f2tf32(va.x);
            p[4]  = f2tf32(va.y);
            p[8]  = f2tf32(va.z);
            p[12] = f2tf32(va.w);
        }
        float4 vb = *reinterpret_cast<const float4*>(
            &B[(size_t)(colBase + row) * K + k0 + (q << 2)]);
        {
            int nt = row >> 3;
            uint32_t* p = &sB[((((((nt << 2) + ks) << 5) + ((row & 7) << 2))) << 1) + e2];
            p[0] = f2tf32(vb.x);
            p[2] = f2tf32(vb.y);
            p[4] = f2tf32(vb.z);
            p[6] = f2tf32(vb.w);
        }
    }
}

// ---------------------------------------------------------------------------
// MLP GEMM: C = act(A @ B^T + bias), tf32 tensor cores.
// blockIdx.z selects branch 0/1. doElu: ELU(alpha=1) or identity.
// ---------------------------------------------------------------------------
__global__ __launch_bounds__(NTHREADS) void gemm_bias_act_mma(
    const float* __restrict__ A0, const float* __restrict__ A1,
    const float* __restrict__ B, const float* __restrict__ bias,
    float* __restrict__ C0, float* __restrict__ C1,
    int K, int Nn, int doElu)
{
    __shared__ uint32_t sA[4096];
    __shared__ uint32_t sB[4096];

    const float* A = (blockIdx.z == 0) ? A0 : A1;
    float* C = (blockIdx.z == 0) ? C0 : C1;

    const int t = threadIdx.x;
    const int wid = t >> 5, lane = t & 31;
    const int wm = wid >> 2, wn = wid & 3;
    const int rowBase = blockIdx.y * BM;
    const int colBase = blockIdx.x * BN;

    float acc[4][4][4];
#pragma unroll
    for (int i = 0; i < 4; i++)
#pragma unroll
        for (int j = 0; j < 4; j++)
#pragma unroll
            for (int r = 0; r < 4; r++) acc[i][j][r] = 0.0f;

    for (int k0 = 0; k0 < K; k0 += BK) {
        fill_tiles(sA, sB, A, B, rowBase, colBase, K, k0, t);
        __syncthreads();

#pragma unroll
        for (int ks = 0; ks < 4; ks++) {
            uint32_t af[4][4];
            uint32_t bf[4][2];
#pragma unroll
            for (int am = 0; am < 4; am++) {
                uint4 v = *reinterpret_cast<const uint4*>(
                    &sA[(((((wm << 2) + am) << 2) + ks) << 5 | lane) << 2]);
                af[am][0] = v.x; af[am][1] = v.y; af[am][2] = v.z; af[am][3] = v.w;
            }
#pragma unroll
            for (int bn = 0; bn < 4; bn++) {
                uint2 v = *reinterpret_cast<const uint2*>(
                    &sB[(((((wn << 2) + bn) << 2) + ks) << 5 | lane) << 1]);
                bf[bn][0] = v.x; bf[bn][1] = v.y;
            }
#pragma unroll
            for (int am = 0; am < 4; am++)
#pragma unroll
                for (int bn = 0; bn < 4; bn++)
                    mma_tf32(acc[am][bn], af[am], bf[bn]);
        }
        __syncthreads();
    }

    // Epilogue: bias + optional ELU
#pragma unroll
    for (int am = 0; am < 4; am++) {
        int row0 = rowBase + wm * 64 + am * 16 + (lane >> 2);
#pragma unroll
        for (int bn = 0; bn < 4; bn++) {
            int col = colBase + wn * 32 + bn * 8 + ((lane & 3) << 1);
            float b0 = bias[col], b1 = bias[col + 1];
            float v0 = acc[am][bn][0] + b0;
            float v1 = acc[am][bn][1] + b1;
            float v2 = acc[am][bn][2] + b0;
            float v3 = acc[am][bn][3] + b1;
            if (doElu) {
                v0 = (v0 > 0.0f) ? v0 : expm1f(v0);
                v1 = (v1 > 0.0f) ? v1 : expm1f(v1);
                v2 = (v2 > 0.0f) ? v2 : expm1f(v2);
                v3 = (v3 > 0.0f) ? v3 : expm1f(v3);
            }
            float2 lo = {v0, v1}, hi = {v2, v3};
            *reinterpret_cast<float2*>(&C[(size_t)row0 * Nn + col]) = lo;
            *reinterpret_cast<float2*>(&C[(size_t)(row0 + 8) * Nn + col]) = hi;
        }
    }
}

// ---------------------------------------------------------------------------
// Row norms (inverse) + zero the S/P accumulators.
// ---------------------------------------------------------------------------
__global__ void norm_init_kernel(const float* __restrict__ z0,
                                 const float* __restrict__ z1)
{
    int b = blockIdx.x;
    int row = (b < NDIM) ? b : (b - NDIM);
    const float* z = (b < NDIM) ? z0 : z1;

    float4 v = *reinterpret_cast<const float4*>(
        &z[(size_t)row * HDIM + threadIdx.x * 4]);
    float ss = v.x * v.x + v.y * v.y + v.z * v.z + v.w * v.w;
#pragma unroll
    for (int off = 16; off; off >>= 1)
        ss += __shfl_xor_sync(0xffffffffu, ss, off);

    __shared__ float sred[4];
    if ((threadIdx.x & 31) == 0) sred[threadIdx.x >> 5] = ss;
    __syncthreads();
    if (threadIdx.x == 0) {
        float tot = sred[0] + sred[1] + sred[2] + sred[3];
        float inv = 1.0f / sqrtf(tot);
        if (b < NDIM) {
            g_inv0[row] = inv;
            g_S[row] = 0.0f;
            g_P[row] = 0.0f;
        } else {
            g_inv1[row] = inv;
        }
    }
}

// ---------------------------------------------------------------------------
// Fused similarity (tf32 mma): dot tile -> exp(cos/tau) -> per-row S/P sums.
// Block-level smem reduction, then one global atomic per row per block.
// ---------------------------------------------------------------------------
__global__ __launch_bounds__(NTHREADS) void sim_fused_mma(
    const float* __restrict__ z0, const float* __restrict__ z1,
    const float* __restrict__ pos)
{
    __shared__ uint32_t sA[4096];
    __shared__ uint32_t sB[4096];
    __shared__ float sS[BM];
    __shared__ float sP[BM];

    const int t = threadIdx.x;
    const int wid = t >> 5, lane = t & 31;
    const int wm = wid >> 2, wn = wid & 3;
    const int rowBase = blockIdx.y * BM;
    const int colBase = blockIdx.x * BN;
    const int K = HDIM;

    if (t < BM) { sS[t] = 0.0f; sP[t] = 0.0f; }

    float acc[4][4][4];
#pragma unroll
    for (int i = 0; i < 4; i++)
#pragma unroll
        for (int j = 0; j < 4; j++)
#pragma unroll
            for (int r = 0; r < 4; r++) acc[i][j][r] = 0.0f;

    for (int k0 = 0; k0 < K; k0 += BK) {
        fill_tiles(sA, sB, z0, z1, rowBase, colBase, K, k0, t);
        __syncthreads();

#pragma unroll
        for (int ks = 0; ks < 4; ks++) {
            uint32_t af[4][4];
            uint32_t bf[4][2];
#pragma unroll
            for (int am = 0; am < 4; am++) {
                uint4 v = *reinterpret_cast<const uint4*>(
                    &sA[(((((wm << 2) + am) << 2) + ks) << 5 | lane) << 2]);
                af[am][0] = v.x; af[am][1] = v.y; af[am][2] = v.z; af[am][3] = v.w;
            }
#pragma unroll
            for (int bn = 0; bn < 4; bn++) {
                uint2 v = *reinterpret_cast<const uint2*>(
                    &sB[(((((wn << 2) + bn) << 2) + ks) << 5 | lane) << 1]);
                bf[bn][0] = v.x; bf[bn][1] = v.y;
            }
#pragma unroll
            for (int am = 0; am < 4; am++)
#pragma unroll
                for (int bn = 0; bn < 4; bn++)
                    mma_tf32(acc[am][bn], af[am], bf[bn]);
        }
        __syncthreads();
    }

    // Epilogue: exp(cos/tau), weight by pos, per-row reduce
#pragma unroll
    for (int am = 0; am < 4; am++) {
        int rloc0 = wm * 64 + am * 16 + (lane >> 2);
        int row0 = rowBase + rloc0;
        float ii0 = g_inv0[row0] * TAU_INV;
        float ii1 = g_inv0[row0 + 8] * TAU_INV;
        float s0 = 0.0f, p0 = 0.0f, s1 = 0.0f, p1 = 0.0f;
#pragma unroll
        for (int bn = 0; bn < 4; bn++) {
            int col = colBase + wn * 32 + bn * 8 + ((lane & 3) << 1);
            float j0 = g_inv1[col];
            float j1 = g_inv1[col + 1];
            float2 pv0 = *reinterpret_cast<const float2*>(
                &pos[(size_t)row0 * NDIM + col]);
            float2 pv1 = *reinterpret_cast<const float2*>(
                &pos[(size_t)(row0 + 8) * NDIM + col]);
            float m;
            m = expf(acc[am][bn][0] * ii0 * j0); s0 += m; p0 += m * pv0.x;
            m = expf(acc[am][bn][1] * ii0 * j1); s0 += m; p0 += m * pv0.y;
            m = expf(acc[am][bn][2] * ii1 * j0); s1 += m; p1 += m * pv1.x;
            m = expf(acc[am][bn][3] * ii1 * j1); s1 += m; p1 += m * pv1.y;
        }
        // reduce across the 4 lanes sharing a row (lane&3 varies)
#pragma unroll
        for (int off = 1; off < 4; off <<= 1) {
            s0 += __shfl_xor_sync(0xffffffffu, s0, off);
            p0 += __shfl_xor_sync(0xffffffffu, p0, off);
            s1 += __shfl_xor_sync(0xffffffffu, s1, off);
            p1 += __shfl_xor_sync(0xffffffffu, p1, off);
        }
        if ((lane & 3) == 0) {
            atomicAdd(&sS[rloc0], s0);
            atomicAdd(&sP[rloc0], p0);
            atomicAdd(&sS[rloc0 + 8], s1);
            atomicAdd(&sP[rloc0 + 8], p1);
        }
    }
    __syncthreads();
    if (t < BM) {
        atomicAdd(&g_S[rowBase + t], sS[t]);
        atomicAdd(&g_P[rowBase + t], sP[t]);
    }
}

// ---------------------------------------------------------------------------
// Final loss: -mean(log(P/(S+eps)+eps))
// ---------------------------------------------------------------------------
__global__ void loss_kernel(float* __restrict__ loss_out)
{
    float local = 0.0f;
    for (int i = threadIdx.x; i < NDIM; i += 256) {
        local += logf(g_P[i] / (g_S[i] + EPSV) + EPSV);
    }
#pragma unroll
    for (int off = 16; off; off >>= 1)
        local += __shfl_xor_sync(0xffffffffu, local, off);

    __shared__ float sred[8];
    if ((threadIdx.x & 31) == 0) sred[threadIdx.x >> 5] = local;
    __syncthreads();
    if (threadIdx.x == 0) {
        float tot = 0.0f;
#pragma unroll
        for (int w = 0; w < 8; w++) tot += sred[w];
        loss_out[0] = -tot / (float)NDIM;
    }
}

// ---------------------------------------------------------------------------
// kernel_launch — inputs: embd0, embd1, pos, W1, b1, W2, b2
// output layout: [z0 (N*H) | z1 (N*H) | loss (1)]
// ---------------------------------------------------------------------------
extern "C" void kernel_launch(void* const* d_in, const int* in_sizes, int n_in,
                              void* d_out, int out_size)
{
    const float* embd0 = (const float*)d_in[0];
    const float* embd1 = (const float*)d_in[1];
    const float* pos   = (const float*)d_in[2];
    const float* W1    = (const float*)d_in[3];
    const float* b1    = (const float*)d_in[4];
    const float* W2    = (const float*)d_in[5];
    const float* b2    = (const float*)d_in[6];

    float* out = (float*)d_out;
    float* z0 = out;
    float* z1 = out + (size_t)NDIM * HDIM;
    float* loss = out + 2ull * NDIM * HDIM;

    float* h = nullptr;
    cudaGetSymbolAddress((void**)&h, g_h);
    float* h0 = h;
    float* h1 = h + (size_t)NDIM * HDIM;

    dim3 blk(NTHREADS);
    dim3 grid_mlp(HDIM / BN, NDIM / BM, 2);   // 4 x 64 x 2
    dim3 grid_sim(NDIM / BN, NDIM / BM);      // 64 x 64

    gemm_bias_act_mma<<<grid_mlp, blk>>>(embd0, embd1, W1, b1, h0, h1,
                                         HDIM, HDIM, 1);
    gemm_bias_act_mma<<<grid_mlp, blk>>>(h0, h1, W2, b2, z0, z1,
                                         HDIM, HDIM, 0);
    norm_init_kernel<<<2 * NDIM, 128>>>(z0, z1);
    sim_fused_mma<<<grid_sim, blk>>>(z0, z1, pos);
    loss_kernel<<<1, 256>>>(loss);
}

// round 5
// speedup vs baseline: 1.9646x; 1.0004x over previous
#include <cuda_runtime.h>
#include <math.h>
#include <stdint.h>

// Problem constants
#define NDIM 8192
#define HDIM 512
#define TAU_INV 2.0f     // 1/0.5
#define EPSV 1e-8f

// Tiling (tensor-core version)
constexpr int BM = 128, BN = 128, BK = 32;
constexpr int NTHREADS = 256;   // 8 warps, arranged 2 (m) x 4 (n); warp tile 64x32

// Scratch (static device memory; no allocation allowed)
__device__ float g_h[2ull * NDIM * HDIM];   // hidden activations (32 MB)
__device__ float g_inv0[NDIM];
__device__ float g_inv1[NDIM];
__device__ float g_S[NDIM];
__device__ float g_P[NDIM];

__device__ __forceinline__ uint32_t f2tf32(float f) {
    uint32_t u;
    asm("cvt.rna.tf32.f32 %0, %1;" : "=r"(u) : "f"(f));
    return u;
}

__device__ __forceinline__ void mma_tf32(float c[4],
                                         const uint32_t a[4],
                                         const uint32_t b[2]) {
    asm volatile(
        "mma.sync.aligned.m16n8k8.row.col.f32.tf32.tf32.f32 "
        "{%0,%1,%2,%3}, {%4,%5,%6,%7}, {%8,%9}, {%0,%1,%2,%3};"
        : "+f"(c[0]), "+f"(c[1]), "+f"(c[2]), "+f"(c[3])
        : "r"(a[0]), "r"(a[1]), "r"(a[2]), "r"(a[3]),
          "r"(b[0]), "r"(b[1]));
}

// ---------------------------------------------------------------------------
// Fragment-ordered smem fill.
// A tile [BM x BK] (row-major source A[row][k]):
//   sA[(((mt*4)+ks)*32 + l)*4 + r], mt=row/16, ks=k/8,
//   l=(row%8)*4 + (k%4), r=((row/8)%2) + 2*((k%8)/4)
// B tile [BN x BK] (row-major source B[n][k]):
//   sB[(((nt*4)+ks)*32 + l)*2 + r], nt=n/8, ks=k/8,
//   l=(n%8)*4 + (k%4), r=(k%8)/4
// Each thread loads 4 float4 along k per tile (128 rows x 8 k-quads).
// ---------------------------------------------------------------------------
__device__ __forceinline__ void fill_tiles(
    uint32_t* sA, uint32_t* sB,
    const float* __restrict__ A, const float* __restrict__ B,
    int rowBase, int colBase, int K, int k0, int t)
{
#pragma unroll
    for (int v = 0; v < 4; v++) {
        int idx = t + v * 256;          // 0..1023
        int row = idx >> 3;             // 0..127
        int q   = idx & 7;              // k-quad (k = 4q..4q+3)
        int ks  = q >> 1;
        int e2  = q & 1;

        float4 va = *reinterpret_cast<const float4*>(
            &A[(size_t)(rowBase + row) * K + k0 + (q << 2)]);
        {
            int mt = row >> 4;
            int rr = row & 15;
            int r  = (rr >> 3) + (e2 << 1);
            uint32_t* p = &sA[(((((mt << 2) + ks) << 5) + ((rr & 7) << 2)) << 2) + r];
            p[0]  = f2tf32(va.x);
            p[4]  = f2tf32(va.y);
            p[8]  = f2tf32(va.z);
            p[12] = f2tf32(va.w);
        }
        float4 vb = *reinterpret_cast<const float4*>(
            &B[(size_t)(colBase + row) * K + k0 + (q << 2)]);
        {
            int nt = row >> 3;
            uint32_t* p = &sB[((((((nt << 2) + ks) << 5) + ((row & 7) << 2))) << 1) + e2];
            p[0] = f2tf32(vb.x);
            p[2] = f2tf32(vb.y);
            p[4] = f2tf32(vb.z);
            p[6] = f2tf32(vb.w);
        }
    }
}

// ---------------------------------------------------------------------------
// MLP GEMM: C = act(A @ B^T + bias), tf32 tensor cores.
// blockIdx.z selects branch 0/1. doElu: ELU(alpha=1) or identity.
// ---------------------------------------------------------------------------
__global__ __launch_bounds__(NTHREADS) void gemm_bias_act_mma(
    const float* __restrict__ A0, const float* __restrict__ A1,
    const float* __restrict__ B, const float* __restrict__ bias,
    float* __restrict__ C0, float* __restrict__ C1,
    int K, int Nn, int doElu)
{
    __shared__ uint32_t sA[4096];
    __shared__ uint32_t sB[4096];

    const float* A = (blockIdx.z == 0) ? A0 : A1;
    float* C = (blockIdx.z == 0) ? C0 : C1;

    const int t = threadIdx.x;
    const int wid = t >> 5, lane = t & 31;
    const int wm = wid >> 2, wn = wid & 3;
    const int rowBase = blockIdx.y * BM;
    const int colBase = blockIdx.x * BN;

    float acc[4][4][4];
#pragma unroll
    for (int i = 0; i < 4; i++)
#pragma unroll
        for (int j = 0; j < 4; j++)
#pragma unroll
            for (int r = 0; r < 4; r++) acc[i][j][r] = 0.0f;

    for (int k0 = 0; k0 < K; k0 += BK) {
        fill_tiles(sA, sB, A, B, rowBase, colBase, K, k0, t);
        __syncthreads();

#pragma unroll
        for (int ks = 0; ks < 4; ks++) {
            uint32_t af[4][4];
            uint32_t bf[4][2];
#pragma unroll
            for (int am = 0; am < 4; am++) {
                uint4 v = *reinterpret_cast<const uint4*>(
                    &sA[(((((wm << 2) + am) << 2) + ks) << 5 | lane) << 2]);
                af[am][0] = v.x; af[am][1] = v.y; af[am][2] = v.z; af[am][3] = v.w;
            }
#pragma unroll
            for (int bn = 0; bn < 4; bn++) {
                uint2 v = *reinterpret_cast<const uint2*>(
                    &sB[(((((wn << 2) + bn) << 2) + ks) << 5 | lane) << 1]);
                bf[bn][0] = v.x; bf[bn][1] = v.y;
            }
#pragma unroll
            for (int am = 0; am < 4; am++)
#pragma unroll
                for (int bn = 0; bn < 4; bn++)
                    mma_tf32(acc[am][bn], af[am], bf[bn]);
        }
        __syncthreads();
    }

    // Epilogue: bias + optional ELU
#pragma unroll
    for (int am = 0; am < 4; am++) {
        int row0 = rowBase + wm * 64 + am * 16 + (lane >> 2);
#pragma unroll
        for (int bn = 0; bn < 4; bn++) {
            int col = colBase + wn * 32 + bn * 8 + ((lane & 3) << 1);
            float b0 = bias[col], b1 = bias[col + 1];
            float v0 = acc[am][bn][0] + b0;
            float v1 = acc[am][bn][1] + b1;
            float v2 = acc[am][bn][2] + b0;
            float v3 = acc[am][bn][3] + b1;
            if (doElu) {
                v0 = (v0 > 0.0f) ? v0 : expm1f(v0);
                v1 = (v1 > 0.0f) ? v1 : expm1f(v1);
                v2 = (v2 > 0.0f) ? v2 : expm1f(v2);
                v3 = (v3 > 0.0f) ? v3 : expm1f(v3);
            }
            float2 lo = {v0, v1}, hi = {v2, v3};
            *reinterpret_cast<float2*>(&C[(size_t)row0 * Nn + col]) = lo;
            *reinterpret_cast<float2*>(&C[(size_t)(row0 + 8) * Nn + col]) = hi;
        }
    }
}

// ---------------------------------------------------------------------------
// Row norms (inverse) + zero the S/P accumulators.
// ---------------------------------------------------------------------------
__global__ void norm_init_kernel(const float* __restrict__ z0,
                                 const float* __restrict__ z1)
{
    int b = blockIdx.x;
    int row = (b < NDIM) ? b : (b - NDIM);
    const float* z = (b < NDIM) ? z0 : z1;

    float4 v = *reinterpret_cast<const float4*>(
        &z[(size_t)row * HDIM + threadIdx.x * 4]);
    float ss = v.x * v.x + v.y * v.y + v.z * v.z + v.w * v.w;
#pragma unroll
    for (int off = 16; off; off >>= 1)
        ss += __shfl_xor_sync(0xffffffffu, ss, off);

    __shared__ float sred[4];
    if ((threadIdx.x & 31) == 0) sred[threadIdx.x >> 5] = ss;
    __syncthreads();
    if (threadIdx.x == 0) {
        float tot = sred[0] + sred[1] + sred[2] + sred[3];
        float inv = 1.0f / sqrtf(tot);
        if (b < NDIM) {
            g_inv0[row] = inv;
            g_S[row] = 0.0f;
            g_P[row] = 0.0f;
        } else {
            g_inv1[row] = inv;
        }
    }
}

// ---------------------------------------------------------------------------
// Fused similarity (tf32 mma): dot tile -> exp(cos/tau) -> per-row S/P sums.
// Block-level smem reduction, then one global atomic per row per block.
// ---------------------------------------------------------------------------
__global__ __launch_bounds__(NTHREADS) void sim_fused_mma(
    const float* __restrict__ z0, const float* __restrict__ z1,
    const float* __restrict__ pos)
{
    __shared__ uint32_t sA[4096];
    __shared__ uint32_t sB[4096];
    __shared__ float sS[BM];
    __shared__ float sP[BM];

    const int t = threadIdx.x;
    const int wid = t >> 5, lane = t & 31;
    const int wm = wid >> 2, wn = wid & 3;
    const int rowBase = blockIdx.y * BM;
    const int colBase = blockIdx.x * BN;
    const int K = HDIM;

    if (t < BM) { sS[t] = 0.0f; sP[t] = 0.0f; }

    float acc[4][4][4];
#pragma unroll
    for (int i = 0; i < 4; i++)
#pragma unroll
        for (int j = 0; j < 4; j++)
#pragma unroll
            for (int r = 0; r < 4; r++) acc[i][j][r] = 0.0f;

    for (int k0 = 0; k0 < K; k0 += BK) {
        fill_tiles(sA, sB, z0, z1, rowBase, colBase, K, k0, t);
        __syncthreads();

#pragma unroll
        for (int ks = 0; ks < 4; ks++) {
            uint32_t af[4][4];
            uint32_t bf[4][2];
#pragma unroll
            for (int am = 0; am < 4; am++) {
                uint4 v = *reinterpret_cast<const uint4*>(
                    &sA[(((((wm << 2) + am) << 2) + ks) << 5 | lane) << 2]);
                af[am][0] = v.x; af[am][1] = v.y; af[am][2] = v.z; af[am][3] = v.w;
            }
#pragma unroll
            for (int bn = 0; bn < 4; bn++) {
                uint2 v = *reinterpret_cast<const uint2*>(
                    &sB[(((((wn << 2) + bn) << 2) + ks) << 5 | lane) << 1]);
                bf[bn][0] = v.x; bf[bn][1] = v.y;
            }
#pragma unroll
            for (int am = 0; am < 4; am++)
#pragma unroll
                for (int bn = 0; bn < 4; bn++)
                    mma_tf32(acc[am][bn], af[am], bf[bn]);
        }
        __syncthreads();
    }

    // Epilogue: exp(cos/tau), weight by pos, per-row reduce
#pragma unroll
    for (int am = 0; am < 4; am++) {
        int rloc0 = wm * 64 + am * 16 + (lane >> 2);
        int row0 = rowBase + rloc0;
        float ii0 = g_inv0[row0] * TAU_INV;
        float ii1 = g_inv0[row0 + 8] * TAU_INV;
        float s0 = 0.0f, p0 = 0.0f, s1 = 0.0f, p1 = 0.0f;
#pragma unroll
        for (int bn = 0; bn < 4; bn++) {
            int col = colBase + wn * 32 + bn * 8 + ((lane & 3) << 1);
            float j0 = g_inv1[col];
            float j1 = g_inv1[col + 1];
            float2 pv0 = *reinterpret_cast<const float2*>(
                &pos[(size_t)row0 * NDIM + col]);
            float2 pv1 = *reinterpret_cast<const float2*>(
                &pos[(size_t)(row0 + 8) * NDIM + col]);
            float m;
            m = expf(acc[am][bn][0] * ii0 * j0); s0 += m; p0 += m * pv0.x;
            m = expf(acc[am][bn][1] * ii0 * j1); s0 += m; p0 += m * pv0.y;
            m = expf(acc[am][bn][2] * ii1 * j0); s1 += m; p1 += m * pv1.x;
            m = expf(acc[am][bn][3] * ii1 * j1); s1 += m; p1 += m * pv1.y;
        }
        // reduce across the 4 lanes sharing a row (lane&3 varies)
#pragma unroll
        for (int off = 1; off < 4; off <<= 1) {
            s0 += __shfl_xor_sync(0xffffffffu, s0, off);
            p0 += __shfl_xor_sync(0xffffffffu, p0, off);
            s1 += __shfl_xor_sync(0xffffffffu, s1, off);
            p1 += __shfl_xor_sync(0xffffffffu, p1, off);
        }
        if ((lane & 3) == 0) {
            atomicAdd(&sS[rloc0], s0);
            atomicAdd(&sP[rloc0], p0);
            atomicAdd(&sS[rloc0 + 8], s1);
            atomicAdd(&sP[rloc0 + 8], p1);
        }
    }
    __syncthreads();
    if (t < BM) {
        atomicAdd(&g_S[rowBase + t], sS[t]);
        atomicAdd(&g_P[rowBase + t], sP[t]);
    }
}

// ---------------------------------------------------------------------------
// Final loss: -mean(log(P/(S+eps)+eps))
// ---------------------------------------------------------------------------
__global__ void loss_kernel(float* __restrict__ loss_out)
{
    float local = 0.0f;
    for (int i = threadIdx.x; i < NDIM; i += 256) {
        local += logf(g_P[i] / (g_S[i] + EPSV) + EPSV);
    }
#pragma unroll
    for (int off = 16; off; off >>= 1)
        local += __shfl_xor_sync(0xffffffffu, local, off);

    __shared__ float sred[8];
    if ((threadIdx.x & 31) == 0) sred[threadIdx.x >> 5] = local;
    __syncthreads();
    if (threadIdx.x == 0) {
        float tot = 0.0f;
#pragma unroll
        for (int w = 0; w < 8; w++) tot += sred[w];
        loss_out[0] = -tot / (float)NDIM;
    }
}

// ---------------------------------------------------------------------------
// kernel_launch — inputs: embd0, embd1, pos, W1, b1, W2, b2
// output layout: [z0 (N*H) | z1 (N*H) | loss (1)]
// ---------------------------------------------------------------------------
extern "C" void kernel_launch(void* const* d_in, const int* in_sizes, int n_in,
                              void* d_out, int out_size)
{
    const float* embd0 = (const float*)d_in[0];
    const float* embd1 = (const float*)d_in[1];
    const float* pos   = (const float*)d_in[2];
    const float* W1    = (const float*)d_in[3];
    const float* b1    = (const float*)d_in[4];
    const float* W2    = (const float*)d_in[5];
    const float* b2    = (const float*)d_in[6];

    float* out = (float*)d_out;
    float* z0 = out;
    float* z1 = out + (size_t)NDIM * HDIM;
    float* loss = out + 2ull * NDIM * HDIM;

    float* h = nullptr;
    cudaGetSymbolAddress((void**)&h, g_h);
    float* h0 = h;
    float* h1 = h + (size_t)NDIM * HDIM;

    dim3 blk(NTHREADS);
    dim3 grid_mlp(HDIM / BN, NDIM / BM, 2);   // 4 x 64 x 2
    dim3 grid_sim(NDIM / BN, NDIM / BM);      // 64 x 64

    gemm_bias_act_mma<<<grid_mlp, blk>>>(embd0, embd1, W1, b1, h0, h1,
                                         HDIM, HDIM, 1);
    gemm_bias_act_mma<<<grid_mlp, blk>>>(h0, h1, W2, b2, z0, z1,
                                         HDIM, HDIM, 0);
    norm_init_kernel<<<2 * NDIM, 128>>>(z0, z1);
    sim_fused_mma<<<grid_sim, blk>>>(z0, z1, pos);
    loss_kernel<<<1, 256>>>(loss);
}